// round 1
// baseline (speedup 1.0000x reference)
#include <cuda_runtime.h>
#include <cstdint>

#define TT   512
#define BB   1024
#define H1   64
#define G1   256     // 4*H1
#define BT1  8
#define H2   32
#define G2   128     // 4*H2
#define BT2  8

// scratch: h1[t][b][j], j in [0,128): fwd half [0,64), rev half [64,128)
__device__ float g_h1[(size_t)TT * BB * 128];

__device__ __forceinline__ float sigm(float x) {
    return __fdividef(1.f, 1.f + __expf(-x));
}
__device__ __forceinline__ float tanh_(float x) {
    // tanh(x) = 1 - 2/(e^{2x}+1); saturates correctly for |x| large
    return 1.f - __fdividef(2.f, __expf(2.f * x) + 1.f);
}

// ---------------------------------------------------------------------------
// Kernel 1: bidirectional layer-1 LSTM. grid = (128, 2), block = 256.
// blockIdx.y = direction (0 fwd, 1 rev). Each block scans T for 8 batches.
// ---------------------------------------------------------------------------
__global__ __launch_bounds__(256, 2)
void lstm1_kernel(const float* __restrict__ x,
                  const float* __restrict__ wih_f, const float* __restrict__ whh_f,
                  const float* __restrict__ b_f,
                  const float* __restrict__ wih_r, const float* __restrict__ whh_r,
                  const float* __restrict__ b_r)
{
    const int dir = blockIdx.y;
    const int b0  = blockIdx.x * BT1;
    const int tid = threadIdx.x;

    const float* wih = dir ? wih_r : wih_f;
    const float* whh = dir ? whh_r : whh_f;
    const float* bb  = dir ? b_r  : b_f;

    __shared__ float sx[BT1][TT];    // 16 KB: x tile
    __shared__ float sh[BT1][H1];    // 2 KB : current h
    __shared__ float sz[BT1][G1];    // 8 KB : gate pre-activations

    // stage x tile: x layout [B, T, 1]
    for (int i = tid; i < BT1 * TT; i += 256) {
        int b = i >> 9, t = i & (TT - 1);
        sx[b][t] = x[(size_t)(b0 + b) * TT + t];
    }
    for (int i = tid; i < BT1 * H1; i += 256) ((float*)sh)[i] = 0.f;

    // per-thread gate row
    const int g = tid;               // 0..255
    float w[H1];
#pragma unroll
    for (int k = 0; k < H1; k++) w[k] = whh[g * H1 + k];
    const float wi = wih[g];
    const float bg = bb[g];

    // cell state for the two cell items this thread owns
    float c0 = 0.f, c1 = 0.f;
    const int cb  = tid >> 6;        // 0..3
    const int ch  = tid & 63;
    const int cb2 = cb + 4;          // 4..7

    __syncthreads();

    for (int tt = 0; tt < TT; ++tt) {
        const int t = dir ? (TT - 1 - tt) : tt;

        // --- recurrent matvec: z[b][g] = x*wih + b + h . Whh[g] ---
        float acc[BT1];
#pragma unroll
        for (int b = 0; b < BT1; b++) acc[b] = fmaf(sx[b][t], wi, bg);
#pragma unroll
        for (int k = 0; k < H1; k += 4) {
#pragma unroll
            for (int b = 0; b < BT1; b++) {
                float4 hv = *(const float4*)&sh[b][k];
                acc[b] = fmaf(hv.x, w[k + 0], acc[b]);
                acc[b] = fmaf(hv.y, w[k + 1], acc[b]);
                acc[b] = fmaf(hv.z, w[k + 2], acc[b]);
                acc[b] = fmaf(hv.w, w[k + 3], acc[b]);
            }
        }
#pragma unroll
        for (int b = 0; b < BT1; b++) sz[b][g] = acc[b];
        __syncthreads();

        // --- cell update: 512 items, 2 per thread ---
        {
            float zi = sz[cb][ch], zf = sz[cb][64 + ch];
            float zg = sz[cb][128 + ch], zo = sz[cb][192 + ch];
            c0 = sigm(zf) * c0 + sigm(zi) * tanh_(zg);
            float hv = sigm(zo) * tanh_(c0);
            sh[cb][ch] = hv;
            g_h1[((size_t)t * BB + (b0 + cb)) * 128 + dir * 64 + ch] = hv;

            float zi2 = sz[cb2][ch], zf2 = sz[cb2][64 + ch];
            float zg2 = sz[cb2][128 + ch], zo2 = sz[cb2][192 + ch];
            c1 = sigm(zf2) * c1 + sigm(zi2) * tanh_(zg2);
            float hv2 = sigm(zo2) * tanh_(c1);
            sh[cb2][ch] = hv2;
            g_h1[((size_t)t * BB + (b0 + cb2)) * 128 + dir * 64 + ch] = hv2;
        }
        __syncthreads();
    }
}

// ---------------------------------------------------------------------------
// Kernel 2: layer-2 forward scan + single reverse step + MLP head.
// grid = 128, block = 256. Thread = (gate g2 = tid&127, half q = tid>>7).
// q=0 owns Wih2f[g2][0:80); q=1 owns Wih2f[g2][80:128) + Whh2f[g2][0:32).
// ---------------------------------------------------------------------------
__global__ __launch_bounds__(256, 2)
void lstm2_kernel(const float* __restrict__ wih2f, const float* __restrict__ whh2f,
                  const float* __restrict__ b2f,
                  const float* __restrict__ wih2r, const float* __restrict__ b2r,
                  const float* __restrict__ w_fc1, const float* __restrict__ b_fc1,
                  const float* __restrict__ w_out, const float* __restrict__ b_out,
                  float* __restrict__ out)
{
    const int b0  = blockIdx.x * BT2;
    const int tid = threadIdx.x;
    const int g2  = tid & 127;
    const int q   = tid >> 7;        // 0 or 1

    __shared__ float sin_[2][BT2][G2];  // double-buffered h1 tile (8 KB)
    __shared__ float sh2[BT2][H2];      // 1 KB
    __shared__ float szA[BT2][G2];      // 4 KB
    __shared__ float szB[BT2][G2];      // 4 KB
    __shared__ float slast[BT2][64];    // 2 KB
    __shared__ float sfc[BT2][64];      // 2 KB

    // weights in registers
    float wI[80];   // input-proj slice
    float wH[32];   // recurrent slice (q==1 only; zero otherwise)
    if (q == 0) {
#pragma unroll
        for (int k = 0; k < 80; k++) wI[k] = wih2f[g2 * G2 + k];
#pragma unroll
        for (int k = 0; k < 32; k++) wH[k] = 0.f;
    } else {
#pragma unroll
        for (int k = 0; k < 48; k++) wI[k] = wih2f[g2 * G2 + 80 + k];
#pragma unroll
        for (int k = 48; k < 80; k++) wI[k] = 0.f;
#pragma unroll
        for (int k = 0; k < 32; k++) wH[k] = whh2f[g2 * H2 + k];
    }
    const float bg = (q == 0) ? b2f[g2] : 0.f;

    for (int i = tid; i < BT2 * H2; i += 256) ((float*)sh2)[i] = 0.f;

    // stage h1[t=0] tile (tile is 1024 contiguous floats)
    {
        const float4* src = (const float4*)(g_h1 + (size_t)0 * BB * 128 + (size_t)b0 * 128);
        ((float4*)sin_[0])[tid] = src[tid];
    }

    float c = 0.f;                    // cell state for item (cb, chh)
    const int cb  = tid >> 5;         // 0..7
    const int chh = tid & 31;

    __syncthreads();

    for (int t = 0; t < TT; ++t) {
        const int cur = t & 1;

        // prefetch next tile into registers
        float4 pre = make_float4(0.f, 0.f, 0.f, 0.f);
        if (t + 1 < TT) {
            const float4* src = (const float4*)(g_h1 + (size_t)(t + 1) * BB * 128 + (size_t)b0 * 128);
            pre = src[tid];
        }

        // --- partial gate sums ---
        float acc[BT2];
#pragma unroll
        for (int b = 0; b < BT2; b++) acc[b] = bg;

        if (q == 0) {
#pragma unroll
            for (int k = 0; k < 80; k += 4) {
#pragma unroll
                for (int b = 0; b < BT2; b++) {
                    float4 v = *(const float4*)&sin_[cur][b][k];
                    acc[b] = fmaf(v.x, wI[k + 0], acc[b]);
                    acc[b] = fmaf(v.y, wI[k + 1], acc[b]);
                    acc[b] = fmaf(v.z, wI[k + 2], acc[b]);
                    acc[b] = fmaf(v.w, wI[k + 3], acc[b]);
                }
            }
        } else {
#pragma unroll
            for (int k = 0; k < 48; k += 4) {
#pragma unroll
                for (int b = 0; b < BT2; b++) {
                    float4 v = *(const float4*)&sin_[cur][b][80 + k];
                    acc[b] = fmaf(v.x, wI[k + 0], acc[b]);
                    acc[b] = fmaf(v.y, wI[k + 1], acc[b]);
                    acc[b] = fmaf(v.z, wI[k + 2], acc[b]);
                    acc[b] = fmaf(v.w, wI[k + 3], acc[b]);
                }
            }
#pragma unroll
            for (int k = 0; k < 32; k += 4) {
#pragma unroll
                for (int b = 0; b < BT2; b++) {
                    float4 v = *(const float4*)&sh2[b][k];
                    acc[b] = fmaf(v.x, wH[k + 0], acc[b]);
                    acc[b] = fmaf(v.y, wH[k + 1], acc[b]);
                    acc[b] = fmaf(v.z, wH[k + 2], acc[b]);
                    acc[b] = fmaf(v.w, wH[k + 3], acc[b]);
                }
            }
        }
        if (q == 0) {
#pragma unroll
            for (int b = 0; b < BT2; b++) szA[b][g2] = acc[b];
        } else {
#pragma unroll
            for (int b = 0; b < BT2; b++) szB[b][g2] = acc[b];
        }
        __syncthreads();

        // --- cell update: 256 items, 1 per thread ---
        {
            float zi = szA[cb][chh]      + szB[cb][chh];
            float zf = szA[cb][32 + chh] + szB[cb][32 + chh];
            float zg = szA[cb][64 + chh] + szB[cb][64 + chh];
            float zo = szA[cb][96 + chh] + szB[cb][96 + chh];
            c = sigm(zf) * c + sigm(zi) * tanh_(zg);
            sh2[cb][chh] = sigm(zo) * tanh_(c);
        }
        // park prefetched tile in the other buffer
        if (t + 1 < TT) ((float4*)sin_[1 - cur])[tid] = pre;
        __syncthreads();
    }
    // here: sh2 = h2_forward final; sin_[1] = h1[T-1] tile.

    // --- layer-2 reverse, single step at t = T-1, h=c=0 ---
    {
        float accr[4];
        const float brv = b2r[g2];
#pragma unroll
        for (int j = 0; j < 4; j++) accr[j] = brv;
        const float* wr = wih2r + g2 * G2;
        for (int k = 0; k < G2; k++) {
            float wv = __ldg(wr + k);
#pragma unroll
            for (int j = 0; j < 4; j++)
                accr[j] = fmaf(sin_[1][4 * q + j][k], wv, accr[j]);
        }
#pragma unroll
        for (int j = 0; j < 4; j++) szA[4 * q + j][g2] = accr[j];
    }
    __syncthreads();
    {
        float zi = szA[cb][chh], zf = szA[cb][32 + chh];
        float zg = szA[cb][64 + chh], zo = szA[cb][96 + chh];
        (void)zf; // c_prev = 0, forget term vanishes
        float cr = sigm(zi) * tanh_(zg);
        float hr = sigm(zo) * tanh_(cr);
        slast[cb][chh]      = sh2[cb][chh];  // forward half
        slast[cb][32 + chh] = hr;            // reverse half
    }
    __syncthreads();

    // --- head: fc1 (64x64) + relu ---
    {
#pragma unroll
        for (int rep = 0; rep < 2; rep++) {
            int item = tid + rep * 256;      // 512 items = 8 b x 64 o
            int b = item >> 6, o = item & 63;
            float a = b_fc1[o];
            const float* wf = w_fc1 + o * 64;
            for (int k = 0; k < 64; k++) a = fmaf(slast[b][k], __ldg(wf + k), a);
            sfc[b][o] = fmaxf(a, 0.f);
        }
    }
    __syncthreads();

    // --- head: output dot + sigmoid ---
    if (tid < BT2) {
        float a = b_out[0];
        for (int k = 0; k < 64; k++) a = fmaf(sfc[tid][k], __ldg(w_out + k), a);
        out[b0 + tid] = sigm(a);
    }
}

// ---------------------------------------------------------------------------
extern "C" void kernel_launch(void* const* d_in, const int* in_sizes, int n_in,
                              void* d_out, int out_size)
{
    (void)in_sizes; (void)n_in; (void)out_size;
    const float* x     = (const float*)d_in[0];
    const float* wih1f = (const float*)d_in[1];
    const float* whh1f = (const float*)d_in[2];
    const float* b1f   = (const float*)d_in[3];
    const float* wih1r = (const float*)d_in[4];
    const float* whh1r = (const float*)d_in[5];
    const float* b1r   = (const float*)d_in[6];
    const float* wih2f = (const float*)d_in[7];
    const float* whh2f = (const float*)d_in[8];
    const float* b2f   = (const float*)d_in[9];
    const float* wih2r = (const float*)d_in[10];
    const float* b2r   = (const float*)d_in[12];
    const float* w_fc1 = (const float*)d_in[13];
    const float* b_fc1 = (const float*)d_in[14];
    const float* w_out = (const float*)d_in[15];
    const float* b_out = (const float*)d_in[16];
    float* out = (float*)d_out;

    lstm1_kernel<<<dim3(BB / BT1, 2), 256>>>(x, wih1f, whh1f, b1f, wih1r, whh1r, b1r);
    lstm2_kernel<<<BB / BT2, 256>>>(wih2f, whh2f, b2f, wih2r, b2r,
                                    w_fc1, b_fc1, w_out, b_out, out);
}

// round 2
// speedup vs baseline: 1.1105x; 1.1105x over previous
#include <cuda_runtime.h>
#include <cstdint>

#define TT   512
#define BB   1024
#define H1   64
#define G1   256     // 4*H1
#define BT1  8
#define H2   32
#define G2   128     // 4*H2
#define BT2  8

typedef unsigned long long ull;

// scratch: h1[t][b][j], j in [0,128): fwd half [0,64), rev half [64,128)
__device__ float g_h1[(size_t)TT * BB * 128];

// ---- fast activations -----------------------------------------------------
__device__ __forceinline__ float tanh_(float x) {
    float y;
    asm("tanh.approx.f32 %0, %1;" : "=f"(y) : "f"(x));
    return y;
}
__device__ __forceinline__ float sigm(float x) {
    return fmaf(tanh_(x * 0.5f), 0.5f, 0.5f);
}

// ---- packed fp32x2 fma ----------------------------------------------------
__device__ __forceinline__ void ffma2(ull& acc, ull a, ull b) {
    asm("fma.rn.f32x2 %0, %1, %2, %0;" : "+l"(acc) : "l"(a), "l"(b));
}
__device__ __forceinline__ ull pack2(float lo, float hi) {
    ull r;
    asm("mov.b64 %0, {%1, %2};" : "=l"(r) : "f"(lo), "f"(hi));
    return r;
}
__device__ __forceinline__ float hadd2(ull v) {
    float lo, hi;
    asm("mov.b64 {%0, %1}, %2;" : "=f"(lo), "=f"(hi) : "l"(v));
    return lo + hi;
}

// ---------------------------------------------------------------------------
// Kernel 1: bidirectional layer-1 LSTM. grid = (128, 2), block = 256.
// Thread = gate row g (0..255). k-dim paired for f32x2.
// ---------------------------------------------------------------------------
__global__ __launch_bounds__(256, 2)
void lstm1_kernel(const float* __restrict__ x,
                  const float* __restrict__ wih_f, const float* __restrict__ whh_f,
                  const float* __restrict__ b_f,
                  const float* __restrict__ wih_r, const float* __restrict__ whh_r,
                  const float* __restrict__ b_r)
{
    const int dir = blockIdx.y;
    const int b0  = blockIdx.x * BT1;
    const int tid = threadIdx.x;

    const float* wih = dir ? wih_r : wih_f;
    const float* whh = dir ? whh_r : whh_f;
    const float* bb  = dir ? b_r  : b_f;

    __shared__ float sx[BT1][TT];    // 16 KB
    __shared__ float sh[BT1][H1];    // 2 KB
    __shared__ float sz[BT1][G1];    // 8 KB

    for (int i = tid; i < BT1 * TT; i += 256) {
        int b = i >> 9, t = i & (TT - 1);
        sx[b][t] = x[(size_t)(b0 + b) * TT + t];
    }
    for (int i = tid; i < BT1 * H1; i += 256) ((float*)sh)[i] = 0.f;

    // per-thread gate row, packed as 32 k-pairs (64 regs)
    const int g = tid;
    ull wp[H1 / 2];
    {
        const ull* wrow = (const ull*)(whh + g * H1);  // 256B-aligned rows
#pragma unroll
        for (int j = 0; j < H1 / 2; j++) wp[j] = wrow[j];
    }
    const float wi = wih[g];
    const float bg = bb[g];

    float c0 = 0.f, c1 = 0.f;
    const int cb  = tid >> 6;        // 0..3
    const int ch  = tid & 63;
    const int cb2 = cb + 4;          // 4..7

    __syncthreads();

    for (int tt = 0; tt < TT; ++tt) {
        const int t = dir ? (TT - 1 - tt) : tt;

        // z[b][g] = x*wi + b + h . Whh[g]   (f32x2, paired over k)
        ull acc2[BT1];
#pragma unroll
        for (int b = 0; b < BT1; b++)
            acc2[b] = pack2(fmaf(sx[b][t], wi, bg), 0.f);

#pragma unroll
        for (int j = 0; j < H1 / 4; j++) {           // 16 float4 groups
#pragma unroll
            for (int b = 0; b < BT1; b++) {
                ulonglong2 hv = *(const ulonglong2*)&sh[b][4 * j];
                ffma2(acc2[b], hv.x, wp[2 * j]);
                ffma2(acc2[b], hv.y, wp[2 * j + 1]);
            }
        }
#pragma unroll
        for (int b = 0; b < BT1; b++) sz[b][g] = hadd2(acc2[b]);
        __syncthreads();

        // cell update: 512 items, 2 per thread
        {
            float zi = sz[cb][ch], zf = sz[cb][64 + ch];
            float zg = sz[cb][128 + ch], zo = sz[cb][192 + ch];
            c0 = sigm(zf) * c0 + sigm(zi) * tanh_(zg);
            float hv = sigm(zo) * tanh_(c0);
            sh[cb][ch] = hv;
            g_h1[((size_t)t * BB + (b0 + cb)) * 128 + dir * 64 + ch] = hv;

            float zi2 = sz[cb2][ch], zf2 = sz[cb2][64 + ch];
            float zg2 = sz[cb2][128 + ch], zo2 = sz[cb2][192 + ch];
            c1 = sigm(zf2) * c1 + sigm(zi2) * tanh_(zg2);
            float hv2 = sigm(zo2) * tanh_(c1);
            sh[cb2][ch] = hv2;
            g_h1[((size_t)t * BB + (b0 + cb2)) * 128 + dir * 64 + ch] = hv2;
        }
        __syncthreads();
    }
}

// ---------------------------------------------------------------------------
// Kernel 2: layer-2 forward scan + single reverse step + MLP head.
// grid = 128, block = 256. Thread = (gate g2 = tid&127, half q = tid>>7).
// q=0 owns Wih2f[g2][0:80); q=1 owns Wih2f[g2][80:128) + Whh2f[g2][0:32).
// ---------------------------------------------------------------------------
__global__ __launch_bounds__(256, 2)
void lstm2_kernel(const float* __restrict__ wih2f, const float* __restrict__ whh2f,
                  const float* __restrict__ b2f,
                  const float* __restrict__ wih2r, const float* __restrict__ b2r,
                  const float* __restrict__ w_fc1, const float* __restrict__ b_fc1,
                  const float* __restrict__ w_out, const float* __restrict__ b_out,
                  float* __restrict__ out)
{
    const int b0  = blockIdx.x * BT2;
    const int tid = threadIdx.x;
    const int g2  = tid & 127;
    const int q   = tid >> 7;

    __shared__ float sin_[2][BT2][G2];  // 8 KB double buffer
    __shared__ float sh2[BT2][H2];      // 1 KB
    __shared__ float szA[BT2][G2];      // 4 KB
    __shared__ float szB[BT2][G2];      // 4 KB
    __shared__ float slast[BT2][64];    // 2 KB
    __shared__ float sfc[BT2][64];      // 2 KB

    // packed weights
    ull wIp[40];   // q=0: 40 pairs (k 0..80); q=1: 24 pairs (k 80..128)
    ull wHp[16];   // q=1: 16 pairs of Whh2f row
    if (q == 0) {
        const ull* wr = (const ull*)(wih2f + g2 * G2);
#pragma unroll
        for (int j = 0; j < 40; j++) wIp[j] = wr[j];
#pragma unroll
        for (int j = 0; j < 16; j++) wHp[j] = 0ULL;
    } else {
        const ull* wr = (const ull*)(wih2f + g2 * G2 + 80);
#pragma unroll
        for (int j = 0; j < 24; j++) wIp[j] = wr[j];
#pragma unroll
        for (int j = 24; j < 40; j++) wIp[j] = 0ULL;
        const ull* hr = (const ull*)(whh2f + g2 * H2);
#pragma unroll
        for (int j = 0; j < 16; j++) wHp[j] = hr[j];
    }
    const float bg = (q == 0) ? b2f[g2] : 0.f;

    for (int i = tid; i < BT2 * H2; i += 256) ((float*)sh2)[i] = 0.f;

    {
        const float4* src = (const float4*)(g_h1 + (size_t)b0 * 128);
        ((float4*)sin_[0])[tid] = src[tid];
    }

    float c = 0.f;
    const int cb  = tid >> 5;
    const int chh = tid & 31;

    __syncthreads();

    for (int t = 0; t < TT; ++t) {
        const int cur = t & 1;

        float4 pre = make_float4(0.f, 0.f, 0.f, 0.f);
        if (t + 1 < TT) {
            const float4* src = (const float4*)(g_h1 + (size_t)(t + 1) * BB * 128 + (size_t)b0 * 128);
            pre = src[tid];
        }

        ull acc2[BT2];
#pragma unroll
        for (int b = 0; b < BT2; b++) acc2[b] = pack2(bg, 0.f);

        if (q == 0) {
#pragma unroll
            for (int j = 0; j < 20; j++) {           // k = 0..80, float4 groups
#pragma unroll
                for (int b = 0; b < BT2; b++) {
                    ulonglong2 v = *(const ulonglong2*)&sin_[cur][b][4 * j];
                    ffma2(acc2[b], v.x, wIp[2 * j]);
                    ffma2(acc2[b], v.y, wIp[2 * j + 1]);
                }
            }
        } else {
#pragma unroll
            for (int j = 0; j < 12; j++) {           // k = 80..128
#pragma unroll
                for (int b = 0; b < BT2; b++) {
                    ulonglong2 v = *(const ulonglong2*)&sin_[cur][b][80 + 4 * j];
                    ffma2(acc2[b], v.x, wIp[2 * j]);
                    ffma2(acc2[b], v.y, wIp[2 * j + 1]);
                }
            }
#pragma unroll
            for (int j = 0; j < 8; j++) {            // recurrent, k = 0..32
#pragma unroll
                for (int b = 0; b < BT2; b++) {
                    ulonglong2 v = *(const ulonglong2*)&sh2[b][4 * j];
                    ffma2(acc2[b], v.x, wHp[2 * j]);
                    ffma2(acc2[b], v.y, wHp[2 * j + 1]);
                }
            }
        }
        if (q == 0) {
#pragma unroll
            for (int b = 0; b < BT2; b++) szA[b][g2] = hadd2(acc2[b]);
        } else {
#pragma unroll
            for (int b = 0; b < BT2; b++) szB[b][g2] = hadd2(acc2[b]);
        }
        __syncthreads();

        {
            float zi = szA[cb][chh]      + szB[cb][chh];
            float zf = szA[cb][32 + chh] + szB[cb][32 + chh];
            float zg = szA[cb][64 + chh] + szB[cb][64 + chh];
            float zo = szA[cb][96 + chh] + szB[cb][96 + chh];
            c = sigm(zf) * c + sigm(zi) * tanh_(zg);
            sh2[cb][chh] = sigm(zo) * tanh_(c);
        }
        if (t + 1 < TT) ((float4*)sin_[1 - cur])[tid] = pre;
        __syncthreads();
    }
    // sh2 = final forward h2; sin_[1] holds the h1[T-1] tile.

    // layer-2 reverse: single step at t = T-1 from h=c=0
    {
        float accr[4];
        const float brv = b2r[g2];
#pragma unroll
        for (int j = 0; j < 4; j++) accr[j] = brv;
        const float* wr = wih2r + g2 * G2;
        for (int k = 0; k < G2; k++) {
            float wv = __ldg(wr + k);
#pragma unroll
            for (int j = 0; j < 4; j++)
                accr[j] = fmaf(sin_[1][4 * q + j][k], wv, accr[j]);
        }
#pragma unroll
        for (int j = 0; j < 4; j++) szA[4 * q + j][g2] = accr[j];
    }
    __syncthreads();
    {
        float zi = szA[cb][chh];
        float zg = szA[cb][64 + chh], zo = szA[cb][96 + chh];
        float cr = sigm(zi) * tanh_(zg);      // c_prev = 0
        float hr = sigm(zo) * tanh_(cr);
        slast[cb][chh]      = sh2[cb][chh];
        slast[cb][32 + chh] = hr;
    }
    __syncthreads();

    // fc1 (64x64) + relu
    {
#pragma unroll
        for (int rep = 0; rep < 2; rep++) {
            int item = tid + rep * 256;
            int b = item >> 6, o = item & 63;
            float a = b_fc1[o];
            const float* wf = w_fc1 + o * 64;
            for (int k = 0; k < 64; k++) a = fmaf(slast[b][k], __ldg(wf + k), a);
            sfc[b][o] = fmaxf(a, 0.f);
        }
    }
    __syncthreads();

    if (tid < BT2) {
        float a = b_out[0];
        for (int k = 0; k < 64; k++) a = fmaf(sfc[tid][k], __ldg(w_out + k), a);
        out[b0 + tid] = sigm(a);
    }
}

// ---------------------------------------------------------------------------
extern "C" void kernel_launch(void* const* d_in, const int* in_sizes, int n_in,
                              void* d_out, int out_size)
{
    (void)in_sizes; (void)n_in; (void)out_size;
    const float* x     = (const float*)d_in[0];
    const float* wih1f = (const float*)d_in[1];
    const float* whh1f = (const float*)d_in[2];
    const float* b1f   = (const float*)d_in[3];
    const float* wih1r = (const float*)d_in[4];
    const float* whh1r = (const float*)d_in[5];
    const float* b1r   = (const float*)d_in[6];
    const float* wih2f = (const float*)d_in[7];
    const float* whh2f = (const float*)d_in[8];
    const float* b2f   = (const float*)d_in[9];
    const float* wih2r = (const float*)d_in[10];
    const float* b2r   = (const float*)d_in[12];
    const float* w_fc1 = (const float*)d_in[13];
    const float* b_fc1 = (const float*)d_in[14];
    const float* w_out = (const float*)d_in[15];
    const float* b_out = (const float*)d_in[16];
    float* out = (float*)d_out;

    lstm1_kernel<<<dim3(BB / BT1, 2), 256>>>(x, wih1f, whh1f, b1f, wih1r, whh1r, b1r);
    lstm2_kernel<<<BB / BT2, 256>>>(wih2f, whh2f, b2f, wih2r, b2r,
                                    w_fc1, b_fc1, w_out, b_out, out);
}

// round 3
// speedup vs baseline: 1.4728x; 1.3262x over previous
#include <cuda_runtime.h>
#include <cstdint>

#define TT   512
#define BB   1024
#define H1   64
#define G1   256     // 4*H1
#define BT1  16
#define H2   32
#define G2   128     // 4*H2
#define BT2  8

typedef unsigned long long ull;

// scratch: h1[t][b][j], j in [0,128): fwd half [0,64), rev half [64,128)
__device__ float g_h1[(size_t)TT * BB * 128];

// ---- fast activations -----------------------------------------------------
__device__ __forceinline__ float tanh_(float x) {
    float y;
    asm("tanh.approx.f32 %0, %1;" : "=f"(y) : "f"(x));
    return y;
}
__device__ __forceinline__ float sigm(float x) {
    return fmaf(tanh_(x * 0.5f), 0.5f, 0.5f);
}

// ---- packed fp32x2 fma ----------------------------------------------------
__device__ __forceinline__ void ffma2(ull& acc, ull a, ull b) {
    asm("fma.rn.f32x2 %0, %1, %2, %0;" : "+l"(acc) : "l"(a), "l"(b));
}
__device__ __forceinline__ ull pack2(float lo, float hi) {
    ull r;
    asm("mov.b64 %0, {%1, %2};" : "=l"(r) : "f"(lo), "f"(hi));
    return r;
}
__device__ __forceinline__ float hadd2(ull v) {
    float lo, hi;
    asm("mov.b64 {%0, %1}, %2;" : "=f"(lo), "=f"(hi) : "l"(v));
    return lo + hi;
}

// ---------------------------------------------------------------------------
// Kernel 1: bidirectional layer-1 LSTM.
// grid = (64, 2), block = 512.  thread = (g = tid&255, half = tid>>8).
// half owns k in [32*half, 32*half+32).  BT1=16 batches per block.
// ---------------------------------------------------------------------------
__global__ __launch_bounds__(512, 1)
void lstm1_kernel(const float* __restrict__ x,
                  const float* __restrict__ wih_f, const float* __restrict__ whh_f,
                  const float* __restrict__ b_f,
                  const float* __restrict__ wih_r, const float* __restrict__ whh_r,
                  const float* __restrict__ b_r)
{
    const int dir  = blockIdx.y;
    const int b0   = blockIdx.x * BT1;
    const int tid  = threadIdx.x;
    const int g    = tid & 255;
    const int half = tid >> 8;

    const float* wih = dir ? wih_r : wih_f;
    const float* whh = dir ? whh_r : whh_f;
    const float* bb  = dir ? b_r  : b_f;

    __shared__ float sxc[BT1][64];      // 4 KB: x chunk (64 timesteps)
    __shared__ float sh[BT1][H1];       // 4 KB
    __shared__ float szA[BT1][G1];      // 16 KB
    __shared__ float szB[BT1][G1];      // 16 KB

    for (int i = tid; i < BT1 * H1; i += 512) ((float*)sh)[i] = 0.f;

    // per-thread weights: 32 k-values = 16 packed pairs (32 regs)
    ull wp[16];
    {
        const ull* wrow = (const ull*)(whh + g * H1 + 32 * half);
#pragma unroll
        for (int j = 0; j < 16; j++) wp[j] = wrow[j];
    }
    const float wi = (half == 0) ? wih[g] : 0.f;
    const float bg = (half == 0) ? bb[g]  : 0.f;

    // cell items: 1024 cells, 2 per thread: (cb, ch) and (cb+8, ch)
    float c0 = 0.f, c1 = 0.f;
    const int cb = tid >> 6;            // 0..7
    const int ch = tid & 63;

    __syncthreads();

    for (int tt = 0; tt < TT; ++tt) {
        const int t = dir ? (TT - 1 - tt) : tt;

        // reload x chunk every 64 steps
        if ((tt & 63) == 0) {
            const int tbase = dir ? (448 - (tt & ~63)) : tt;
            const int b  = tid >> 6;        // 0..7, two rows per thread
            const int to = tid & 63;
            sxc[b][to]     = x[(size_t)(b0 + b) * TT + tbase + to];
            sxc[b + 8][to] = x[(size_t)(b0 + b + 8) * TT + tbase + to];
            __syncthreads();
        }
        const int ts = t & 63;

        // partial gate sums over this thread's k-slice
        ull acc2[BT1];
        if (half == 0) {
#pragma unroll
            for (int b = 0; b < BT1; b++)
                acc2[b] = pack2(fmaf(sxc[b][ts], wi, bg), 0.f);
        } else {
#pragma unroll
            for (int b = 0; b < BT1; b++) acc2[b] = 0ULL;
        }
#pragma unroll
        for (int j = 0; j < 8; j++) {        // 8 float4 groups of k
#pragma unroll
            for (int b = 0; b < BT1; b++) {
                ulonglong2 hv = *(const ulonglong2*)&sh[b][32 * half + 4 * j];
                ffma2(acc2[b], hv.x, wp[2 * j]);
                ffma2(acc2[b], hv.y, wp[2 * j + 1]);
            }
        }
        if (half == 0) {
#pragma unroll
            for (int b = 0; b < BT1; b++) szA[b][g] = hadd2(acc2[b]);
        } else {
#pragma unroll
            for (int b = 0; b < BT1; b++) szB[b][g] = hadd2(acc2[b]);
        }
        __syncthreads();

        // cell update: 1024 cells, 2 per thread
        {
            float zi = szA[cb][ch]       + szB[cb][ch];
            float zf = szA[cb][64 + ch]  + szB[cb][64 + ch];
            float zg = szA[cb][128 + ch] + szB[cb][128 + ch];
            float zo = szA[cb][192 + ch] + szB[cb][192 + ch];
            c0 = sigm(zf) * c0 + sigm(zi) * tanh_(zg);
            float hv = sigm(zo) * tanh_(c0);
            sh[cb][ch] = hv;
            g_h1[((size_t)t * BB + (b0 + cb)) * 128 + dir * 64 + ch] = hv;

            int cb2 = cb + 8;
            float zi2 = szA[cb2][ch]       + szB[cb2][ch];
            float zf2 = szA[cb2][64 + ch]  + szB[cb2][64 + ch];
            float zg2 = szA[cb2][128 + ch] + szB[cb2][128 + ch];
            float zo2 = szA[cb2][192 + ch] + szB[cb2][192 + ch];
            c1 = sigm(zf2) * c1 + sigm(zi2) * tanh_(zg2);
            float hv2 = sigm(zo2) * tanh_(c1);
            sh[cb2][ch] = hv2;
            g_h1[((size_t)t * BB + (b0 + cb2)) * 128 + dir * 64 + ch] = hv2;
        }
        __syncthreads();
    }
}

// ---------------------------------------------------------------------------
// Kernel 2: layer-2 forward scan + single reverse step + MLP head.
// grid = 128, block = 512.  thread = (g2 = tid&127, q = tid>>7 in 0..3).
// k-dim (160 = 128 input + 32 recurrent) split 40 per q:
//   q0: inp[0,40)  q1: inp[40,80)  q2: inp[80,120)  q3: inp[120,128)+rec[0,32)
// ---------------------------------------------------------------------------
__global__ __launch_bounds__(512, 1)
void lstm2_kernel(const float* __restrict__ wih2f, const float* __restrict__ whh2f,
                  const float* __restrict__ b2f,
                  const float* __restrict__ wih2r, const float* __restrict__ b2r,
                  const float* __restrict__ w_fc1, const float* __restrict__ b_fc1,
                  const float* __restrict__ w_out, const float* __restrict__ b_out,
                  float* __restrict__ out)
{
    const int b0  = blockIdx.x * BT2;
    const int tid = threadIdx.x;
    const int g2  = tid & 127;
    const int q   = tid >> 7;

    __shared__ float sin_[2][BT2][G2];  // 8 KB double buffer
    __shared__ float sh2[BT2][H2];      // 1 KB
    __shared__ float sz[4][BT2][G2];    // 16 KB partials
    __shared__ float slast[BT2][64];    // 2 KB
    __shared__ float sfc[BT2][64];      // 2 KB

    // packed weights: 40 k-values = 20 pairs (40 regs)
    ull wq[20];
    if (q < 3) {
        const ull* wr = (const ull*)(wih2f + g2 * G2 + 40 * q);
#pragma unroll
        for (int j = 0; j < 20; j++) wq[j] = wr[j];
    } else {
        const ull* wr = (const ull*)(wih2f + g2 * G2 + 120);
#pragma unroll
        for (int j = 0; j < 4; j++) wq[j] = wr[j];
        const ull* hr = (const ull*)(whh2f + g2 * H2);
#pragma unroll
        for (int j = 0; j < 16; j++) wq[4 + j] = hr[j];
    }
    const float bg = (q == 0) ? b2f[g2] : 0.f;

    for (int i = tid; i < BT2 * H2; i += 512) ((float*)sh2)[i] = 0.f;

    // stage h1[t=0] tile (1024 contiguous floats), 2 per thread
    {
        const float2* src = (const float2*)(g_h1 + (size_t)b0 * 128);
        ((float2*)sin_[0])[tid] = src[tid];
    }

    float c = 0.f;
    const int cb  = tid >> 5;       // valid when tid < 256
    const int chh = tid & 31;

    __syncthreads();

    for (int t = 0; t < TT; ++t) {
        const int cur = t & 1;

        float2 pre = make_float2(0.f, 0.f);
        if (t + 1 < TT) {
            const float2* src = (const float2*)(g_h1 + (size_t)(t + 1) * BB * 128 + (size_t)b0 * 128);
            pre = src[tid];
        }

        ull acc2[BT2];
#pragma unroll
        for (int b = 0; b < BT2; b++) acc2[b] = pack2(bg, 0.f);

        if (q < 3) {
#pragma unroll
            for (int j = 0; j < 10; j++) {       // 10 float4 groups
#pragma unroll
                for (int b = 0; b < BT2; b++) {
                    ulonglong2 v = *(const ulonglong2*)&sin_[cur][b][40 * q + 4 * j];
                    ffma2(acc2[b], v.x, wq[2 * j]);
                    ffma2(acc2[b], v.y, wq[2 * j + 1]);
                }
            }
        } else {
#pragma unroll
            for (int j = 0; j < 2; j++) {        // inp k = 120..128
#pragma unroll
                for (int b = 0; b < BT2; b++) {
                    ulonglong2 v = *(const ulonglong2*)&sin_[cur][b][120 + 4 * j];
                    ffma2(acc2[b], v.x, wq[2 * j]);
                    ffma2(acc2[b], v.y, wq[2 * j + 1]);
                }
            }
#pragma unroll
            for (int j = 0; j < 8; j++) {        // recurrent k = 0..32
#pragma unroll
                for (int b = 0; b < BT2; b++) {
                    ulonglong2 v = *(const ulonglong2*)&sh2[b][4 * j];
                    ffma2(acc2[b], v.x, wq[4 + 2 * j]);
                    ffma2(acc2[b], v.y, wq[4 + 2 * j + 1]);
                }
            }
        }
#pragma unroll
        for (int b = 0; b < BT2; b++) sz[q][b][g2] = hadd2(acc2[b]);
        __syncthreads();

        // cell update: 256 cells, threads 0..255
        if (tid < 256) {
            float zi = sz[0][cb][chh]      + sz[1][cb][chh]      + sz[2][cb][chh]      + sz[3][cb][chh];
            float zf = sz[0][cb][32 + chh] + sz[1][cb][32 + chh] + sz[2][cb][32 + chh] + sz[3][cb][32 + chh];
            float zg = sz[0][cb][64 + chh] + sz[1][cb][64 + chh] + sz[2][cb][64 + chh] + sz[3][cb][64 + chh];
            float zo = sz[0][cb][96 + chh] + sz[1][cb][96 + chh] + sz[2][cb][96 + chh] + sz[3][cb][96 + chh];
            c = sigm(zf) * c + sigm(zi) * tanh_(zg);
            sh2[cb][chh] = sigm(zo) * tanh_(c);
        }
        if (t + 1 < TT) ((float2*)sin_[1 - cur])[tid] = pre;
        __syncthreads();
    }
    // sh2 = final forward h2; sin_[1] holds the h1[T-1] tile.

    // layer-2 reverse: single step at t = T-1 from h=c=0.
    // thread = (g2, br = q in 0..3): batches br and br+4
    {
        const float brv = b2r[g2];
        float a0 = brv, a1 = brv;
        const float* wr = wih2r + g2 * G2;
        for (int k = 0; k < G2; k++) {
            float wv = __ldg(wr + k);
            a0 = fmaf(sin_[1][q][k],     wv, a0);
            a1 = fmaf(sin_[1][q + 4][k], wv, a1);
        }
        sz[0][q][g2]     = a0;
        sz[0][q + 4][g2] = a1;
    }
    __syncthreads();
    if (tid < 256) {
        float zi = sz[0][cb][chh];
        float zg = sz[0][cb][64 + chh], zo = sz[0][cb][96 + chh];
        float cr = sigm(zi) * tanh_(zg);      // c_prev = 0
        float hr = sigm(zo) * tanh_(cr);
        slast[cb][chh]      = sh2[cb][chh];
        slast[cb][32 + chh] = hr;
    }
    __syncthreads();

    // fc1 (64x64) + relu: 512 items, 1 per thread
    {
        int b = tid >> 6, o = tid & 63;
        float a = b_fc1[o];
        const float* wf = w_fc1 + o * 64;
        for (int k = 0; k < 64; k++) a = fmaf(slast[b][k], __ldg(wf + k), a);
        sfc[b][o] = fmaxf(a, 0.f);
    }
    __syncthreads();

    if (tid < BT2) {
        float a = b_out[0];
        for (int k = 0; k < 64; k++) a = fmaf(sfc[tid][k], __ldg(w_out + k), a);
        out[b0 + tid] = sigm(a);
    }
}

// ---------------------------------------------------------------------------
extern "C" void kernel_launch(void* const* d_in, const int* in_sizes, int n_in,
                              void* d_out, int out_size)
{
    (void)in_sizes; (void)n_in; (void)out_size;
    const float* x     = (const float*)d_in[0];
    const float* wih1f = (const float*)d_in[1];
    const float* whh1f = (const float*)d_in[2];
    const float* b1f   = (const float*)d_in[3];
    const float* wih1r = (const float*)d_in[4];
    const float* whh1r = (const float*)d_in[5];
    const float* b1r   = (const float*)d_in[6];
    const float* wih2f = (const float*)d_in[7];
    const float* whh2f = (const float*)d_in[8];
    const float* b2f   = (const float*)d_in[9];
    const float* wih2r = (const float*)d_in[10];
    const float* b2r   = (const float*)d_in[12];
    const float* w_fc1 = (const float*)d_in[13];
    const float* b_fc1 = (const float*)d_in[14];
    const float* w_out = (const float*)d_in[15];
    const float* b_out = (const float*)d_in[16];
    float* out = (float*)d_out;

    lstm1_kernel<<<dim3(BB / BT1, 2), 512>>>(x, wih1f, whh1f, b1f, wih1r, whh1r, b1r);
    lstm2_kernel<<<BB / BT2, 512>>>(wih2f, whh2f, b2f, wih2r, b2r,
                                    w_fc1, b_fc1, w_out, b_out, out);
}

// round 4
// speedup vs baseline: 1.9347x; 1.3137x over previous
#include <cuda_runtime.h>
#include <cstdint>

#define TT   512
#define BB   1024
#define H1   64
#define G1   256     // 4*H1
#define BT1  8
#define H2   32
#define G2   128     // 4*H2
#define BT2  4

typedef unsigned long long ull;

// scratch: h1[t][b][j], j in [0,128): fwd half [0,64), rev half [64,128)
__device__ float g_h1[(size_t)TT * BB * 128];

// ---- fast activations -----------------------------------------------------
__device__ __forceinline__ float tanh_(float x) {
    float y;
    asm("tanh.approx.f32 %0, %1;" : "=f"(y) : "f"(x));
    return y;
}
__device__ __forceinline__ float sigm(float x) {
    return fmaf(tanh_(x * 0.5f), 0.5f, 0.5f);
}

// ---- packed fp32x2 fma ----------------------------------------------------
__device__ __forceinline__ void ffma2(ull& acc, ull a, ull b) {
    asm("fma.rn.f32x2 %0, %1, %2, %0;" : "+l"(acc) : "l"(a), "l"(b));
}
__device__ __forceinline__ ull pack2(float lo, float hi) {
    ull r;
    asm("mov.b64 %0, {%1, %2};" : "=l"(r) : "f"(lo), "f"(hi));
    return r;
}
__device__ __forceinline__ float hadd2(ull v) {
    float lo, hi;
    asm("mov.b64 {%0, %1}, %2;" : "=f"(lo), "=f"(hi) : "l"(v));
    return lo + hi;
}

// ---------------------------------------------------------------------------
// Kernel 1: bidirectional layer-1 LSTM.
// grid = (128, 2), block = 256.  thread = (gp = tid&127, half = tid>>7).
// Thread owns gates {2gp, 2gp+1}, k-slice [32*half, 32*half+32). BT1=8.
// ---------------------------------------------------------------------------
__global__ __launch_bounds__(256, 2)
void lstm1_kernel(const float* __restrict__ x,
                  const float* __restrict__ wih_f, const float* __restrict__ whh_f,
                  const float* __restrict__ b_f,
                  const float* __restrict__ wih_r, const float* __restrict__ whh_r,
                  const float* __restrict__ b_r)
{
    const int dir  = blockIdx.y;
    const int b0   = blockIdx.x * BT1;
    const int tid  = threadIdx.x;
    const int gp   = tid & 127;
    const int half = tid >> 7;
    const int g0   = 2 * gp;
    const int g1   = 2 * gp + 1;

    const float* wih = dir ? wih_r : wih_f;
    const float* whh = dir ? whh_r : whh_f;
    const float* bb  = dir ? b_r  : b_f;

    __shared__ float sxc[BT1][64];      // 2 KB: x chunk (64 timesteps)
    __shared__ float sh[BT1][H1];       // 2 KB
    __shared__ float szA[BT1][G1];      // 8 KB
    __shared__ float szB[BT1][G1];      // 8 KB

    for (int i = tid; i < BT1 * H1; i += 256) ((float*)sh)[i] = 0.f;

    // weights: 2 gate rows x 32 k = 32 packed pairs (64 regs)
    ull wp0[16], wp1[16];
    {
        const ull* w0 = (const ull*)(whh + g0 * H1 + 32 * half);
        const ull* w1 = (const ull*)(whh + g1 * H1 + 32 * half);
#pragma unroll
        for (int j = 0; j < 16; j++) { wp0[j] = w0[j]; wp1[j] = w1[j]; }
    }
    const float wi0 = (half == 0) ? wih[g0] : 0.f;
    const float wi1 = (half == 0) ? wih[g1] : 0.f;
    const float bg0 = (half == 0) ? bb[g0]  : 0.f;
    const float bg1 = (half == 0) ? bb[g1]  : 0.f;

    // cell items: 512 cells, 2 per thread: (cb, ch) and (cb+4, ch)
    float c0 = 0.f, c1 = 0.f;
    const int cb = tid >> 6;            // 0..3
    const int ch = tid & 63;

    __syncthreads();

    for (int tt = 0; tt < TT; ++tt) {
        const int t = dir ? (TT - 1 - tt) : tt;

        // reload x chunk every 64 steps (2 barriers since last read -> safe)
        if ((tt & 63) == 0) {
            const int tbase = dir ? (448 - tt) : tt;
            for (int i = tid; i < BT1 * 64; i += 256) {
                int b = i >> 6, to = i & 63;
                sxc[b][to] = x[(size_t)(b0 + b) * TT + tbase + to];
            }
            __syncthreads();
        }
        const int ts = t & 63;

        // partial gate sums over this thread's k-slice, 2 gates
        ull acc0[BT1], acc1[BT1];
        if (half == 0) {
#pragma unroll
            for (int b = 0; b < BT1; b++) {
                acc0[b] = pack2(fmaf(sxc[b][ts], wi0, bg0), 0.f);
                acc1[b] = pack2(fmaf(sxc[b][ts], wi1, bg1), 0.f);
            }
        } else {
#pragma unroll
            for (int b = 0; b < BT1; b++) { acc0[b] = 0ULL; acc1[b] = 0ULL; }
        }
#pragma unroll
        for (int j = 0; j < 8; j++) {        // 8 float4 groups of k
#pragma unroll
            for (int b = 0; b < BT1; b++) {
                ulonglong2 hv = *(const ulonglong2*)&sh[b][32 * half + 4 * j];
                ffma2(acc0[b], hv.x, wp0[2 * j]);
                ffma2(acc0[b], hv.y, wp0[2 * j + 1]);
                ffma2(acc1[b], hv.x, wp1[2 * j]);
                ffma2(acc1[b], hv.y, wp1[2 * j + 1]);
            }
        }
        {
            float* dst = half ? &szB[0][0] : &szA[0][0];
#pragma unroll
            for (int b = 0; b < BT1; b++) {
                *(ull*)(dst + b * G1 + 2 * gp) = pack2(hadd2(acc0[b]), hadd2(acc1[b]));
            }
        }
        __syncthreads();

        // cell update: 512 cells, 2 per thread
        {
            float zi = szA[cb][ch]       + szB[cb][ch];
            float zf = szA[cb][64 + ch]  + szB[cb][64 + ch];
            float zg = szA[cb][128 + ch] + szB[cb][128 + ch];
            float zo = szA[cb][192 + ch] + szB[cb][192 + ch];
            c0 = sigm(zf) * c0 + sigm(zi) * tanh_(zg);
            float hv = sigm(zo) * tanh_(c0);
            sh[cb][ch] = hv;
            g_h1[((size_t)t * BB + (b0 + cb)) * 128 + dir * 64 + ch] = hv;

            int cb2 = cb + 4;
            float zi2 = szA[cb2][ch]       + szB[cb2][ch];
            float zf2 = szA[cb2][64 + ch]  + szB[cb2][64 + ch];
            float zg2 = szA[cb2][128 + ch] + szB[cb2][128 + ch];
            float zo2 = szA[cb2][192 + ch] + szB[cb2][192 + ch];
            c1 = sigm(zf2) * c1 + sigm(zi2) * tanh_(zg2);
            float hv2 = sigm(zo2) * tanh_(c1);
            sh[cb2][ch] = hv2;
            g_h1[((size_t)t * BB + (b0 + cb2)) * 128 + dir * 64 + ch] = hv2;
        }
        __syncthreads();
    }
}

// ---------------------------------------------------------------------------
// Kernel 2: layer-2 forward scan + single reverse step + MLP head.
// grid = 256, block = 256.  thread = (gp = tid&63, q = tid>>6 in 0..3).
// Thread owns gates {2gp, 2gp+1}; k-dim (160 = 128 inp + 32 rec) split 40/q:
//   q0: inp[0,40)  q1: inp[40,80)  q2: inp[80,120)  q3: inp[120,128)+rec[0,32)
// ---------------------------------------------------------------------------
__global__ __launch_bounds__(256, 2)
void lstm2_kernel(const float* __restrict__ wih2f, const float* __restrict__ whh2f,
                  const float* __restrict__ b2f,
                  const float* __restrict__ wih2r, const float* __restrict__ b2r,
                  const float* __restrict__ w_fc1, const float* __restrict__ b_fc1,
                  const float* __restrict__ w_out, const float* __restrict__ b_out,
                  float* __restrict__ out)
{
    const int b0  = blockIdx.x * BT2;
    const int tid = threadIdx.x;
    const int gp  = tid & 63;
    const int q   = tid >> 6;
    const int g0  = 2 * gp;
    const int g1  = 2 * gp + 1;

    __shared__ float sin_[2][BT2][G2];  // 4 KB double buffer
    __shared__ float sh2[BT2][H2];      // 512 B
    __shared__ float sz[4][BT2][G2];    // 8 KB partials
    __shared__ float slast[BT2][64];    // 1 KB
    __shared__ float sfc[BT2][64];      // 1 KB

    // weights: 2 gates x 40 k = 40 packed pairs (80 regs)
    ull wq0[20], wq1[20];
    if (q < 3) {
        const ull* w0 = (const ull*)(wih2f + g0 * G2 + 40 * q);
        const ull* w1 = (const ull*)(wih2f + g1 * G2 + 40 * q);
#pragma unroll
        for (int j = 0; j < 20; j++) { wq0[j] = w0[j]; wq1[j] = w1[j]; }
    } else {
        const ull* w0 = (const ull*)(wih2f + g0 * G2 + 120);
        const ull* w1 = (const ull*)(wih2f + g1 * G2 + 120);
#pragma unroll
        for (int j = 0; j < 4; j++) { wq0[j] = w0[j]; wq1[j] = w1[j]; }
        const ull* h0 = (const ull*)(whh2f + g0 * H2);
        const ull* h1 = (const ull*)(whh2f + g1 * H2);
#pragma unroll
        for (int j = 0; j < 16; j++) { wq0[4 + j] = h0[j]; wq1[4 + j] = h1[j]; }
    }
    const float bg0 = (q == 0) ? b2f[g0] : 0.f;
    const float bg1 = (q == 0) ? b2f[g1] : 0.f;

    for (int i = tid; i < BT2 * H2; i += 256) ((float*)sh2)[i] = 0.f;

    // stage h1[t=0] tile (512 contiguous floats), float2 per thread
    {
        const float2* src = (const float2*)(g_h1 + (size_t)b0 * 128);
        ((float2*)sin_[0])[tid] = src[tid];
    }

    float c = 0.f;
    const int cbb = tid >> 5;       // valid when tid < 128
    const int chh = tid & 31;

    __syncthreads();

    for (int t = 0; t < TT; ++t) {
        const int cur = t & 1;

        float2 pre = make_float2(0.f, 0.f);
        if (t + 1 < TT) {
            const float2* src = (const float2*)(g_h1 + (size_t)(t + 1) * BB * 128 + (size_t)b0 * 128);
            pre = src[tid];
        }

        ull acc0[BT2], acc1[BT2];
#pragma unroll
        for (int b = 0; b < BT2; b++) {
            acc0[b] = pack2(bg0, 0.f);
            acc1[b] = pack2(bg1, 0.f);
        }

        if (q < 3) {
#pragma unroll
            for (int j = 0; j < 10; j++) {       // 10 float4 groups
#pragma unroll
                for (int b = 0; b < BT2; b++) {
                    ulonglong2 v = *(const ulonglong2*)&sin_[cur][b][40 * q + 4 * j];
                    ffma2(acc0[b], v.x, wq0[2 * j]);
                    ffma2(acc0[b], v.y, wq0[2 * j + 1]);
                    ffma2(acc1[b], v.x, wq1[2 * j]);
                    ffma2(acc1[b], v.y, wq1[2 * j + 1]);
                }
            }
        } else {
#pragma unroll
            for (int j = 0; j < 2; j++) {        // inp k = 120..128
#pragma unroll
                for (int b = 0; b < BT2; b++) {
                    ulonglong2 v = *(const ulonglong2*)&sin_[cur][b][120 + 4 * j];
                    ffma2(acc0[b], v.x, wq0[2 * j]);
                    ffma2(acc0[b], v.y, wq0[2 * j + 1]);
                    ffma2(acc1[b], v.x, wq1[2 * j]);
                    ffma2(acc1[b], v.y, wq1[2 * j + 1]);
                }
            }
#pragma unroll
            for (int j = 0; j < 8; j++) {        // recurrent k = 0..32
#pragma unroll
                for (int b = 0; b < BT2; b++) {
                    ulonglong2 v = *(const ulonglong2*)&sh2[b][4 * j];
                    ffma2(acc0[b], v.x, wq0[4 + 2 * j]);
                    ffma2(acc0[b], v.y, wq0[4 + 2 * j + 1]);
                    ffma2(acc1[b], v.x, wq1[4 + 2 * j]);
                    ffma2(acc1[b], v.y, wq1[4 + 2 * j + 1]);
                }
            }
        }
#pragma unroll
        for (int b = 0; b < BT2; b++) {
            *(ull*)&sz[q][b][2 * gp] = pack2(hadd2(acc0[b]), hadd2(acc1[b]));
        }
        __syncthreads();

        // cell update: 128 cells, threads 0..127
        if (tid < 128) {
            float zi = sz[0][cbb][chh]      + sz[1][cbb][chh]      + sz[2][cbb][chh]      + sz[3][cbb][chh];
            float zf = sz[0][cbb][32 + chh] + sz[1][cbb][32 + chh] + sz[2][cbb][32 + chh] + sz[3][cbb][32 + chh];
            float zg = sz[0][cbb][64 + chh] + sz[1][cbb][64 + chh] + sz[2][cbb][64 + chh] + sz[3][cbb][64 + chh];
            float zo = sz[0][cbb][96 + chh] + sz[1][cbb][96 + chh] + sz[2][cbb][96 + chh] + sz[3][cbb][96 + chh];
            c = sigm(zf) * c + sigm(zi) * tanh_(zg);
            sh2[cbb][chh] = sigm(zo) * tanh_(c);
        }
        if (t + 1 < TT) ((float2*)sin_[1 - cur])[tid] = pre;
        __syncthreads();
    }
    // sh2 = final forward h2; sin_[1] holds the h1[T-1] tile.

    // layer-2 reverse: single step at t = T-1 from h=c=0.
    // thread = (g2 = tid&127, rb = tid>>7): batches 2*rb, 2*rb+1
    {
        const int g2 = tid & 127;
        const int rb = tid >> 7;
        const float brv = b2r[g2];
        float a0 = brv, a1 = brv;
        const float* wr = wih2r + g2 * G2;
        for (int k = 0; k < G2; k++) {
            float wv = __ldg(wr + k);
            a0 = fmaf(sin_[1][2 * rb][k],     wv, a0);
            a1 = fmaf(sin_[1][2 * rb + 1][k], wv, a1);
        }
        sz[0][2 * rb][g2]     = a0;
        sz[0][2 * rb + 1][g2] = a1;
    }
    __syncthreads();
    if (tid < 128) {
        float zi = sz[0][cbb][chh];
        float zg = sz[0][cbb][64 + chh], zo = sz[0][cbb][96 + chh];
        float cr = sigm(zi) * tanh_(zg);      // c_prev = 0
        float hr = sigm(zo) * tanh_(cr);
        slast[cbb][chh]      = sh2[cbb][chh];
        slast[cbb][32 + chh] = hr;
    }
    __syncthreads();

    // fc1 (64x64) + relu: 256 items, 1 per thread
    {
        int b = tid >> 6, o = tid & 63;
        float a = b_fc1[o];
        const float* wf = w_fc1 + o * 64;
        for (int k = 0; k < 64; k++) a = fmaf(slast[b][k], __ldg(wf + k), a);
        sfc[b][o] = fmaxf(a, 0.f);
    }
    __syncthreads();

    if (tid < BT2) {
        float a = b_out[0];
        for (int k = 0; k < 64; k++) a = fmaf(sfc[tid][k], __ldg(w_out + k), a);
        out[b0 + tid] = sigm(a);
    }
}

// ---------------------------------------------------------------------------
extern "C" void kernel_launch(void* const* d_in, const int* in_sizes, int n_in,
                              void* d_out, int out_size)
{
    (void)in_sizes; (void)n_in; (void)out_size;
    const float* x     = (const float*)d_in[0];
    const float* wih1f = (const float*)d_in[1];
    const float* whh1f = (const float*)d_in[2];
    const float* b1f   = (const float*)d_in[3];
    const float* wih1r = (const float*)d_in[4];
    const float* whh1r = (const float*)d_in[5];
    const float* b1r   = (const float*)d_in[6];
    const float* wih2f = (const float*)d_in[7];
    const float* whh2f = (const float*)d_in[8];
    const float* b2f   = (const float*)d_in[9];
    const float* wih2r = (const float*)d_in[10];
    const float* b2r   = (const float*)d_in[12];
    const float* w_fc1 = (const float*)d_in[13];
    const float* b_fc1 = (const float*)d_in[14];
    const float* w_out = (const float*)d_in[15];
    const float* b_out = (const float*)d_in[16];
    float* out = (float*)d_out;

    lstm1_kernel<<<dim3(BB / BT1, 2), 256>>>(x, wih1f, whh1f, b1f, wih1r, whh1r, b1r);
    lstm2_kernel<<<BB / BT2, 256>>>(wih2f, whh2f, b2f, wih2r, b2r,
                                    w_fc1, b_fc1, w_out, b_out, out);
}